// round 6
// baseline (speedup 1.0000x reference)
#include <cuda_runtime.h>
#include <cuda_bf16.h>
#include <math.h>

// ---------------- problem constants ----------------
#define BS_     2
#define SEQ_    2048
#define T_      (BS_*SEQ_)      // 4096 tokens
#define DIM_    2048
#define NH_     16
#define QLORA_  1536
#define KVLORA_ 512
#define NOPE_   128
#define ROPE_   64
#define QKHD_   192             // NOPE+ROPE
#define VHD_    128

// ---------------- scratch (static device globals; no runtime alloc) ----------------
__device__ float g_qa [T_*QLORA_];            // q after a-proj (+rmsnorm in place)
__device__ float g_q  [T_*NH_*QKHD_];         // q after b-proj (+rope in place)
__device__ float g_kva[T_*(KVLORA_+ROPE_)];   // kv_a output; last 64 = k_pe (+rope)
__device__ float g_kvn[T_*KVLORA_];           // rmsnorm(kv_c)
__device__ float g_kvb[T_*NH_*(NOPE_+VHD_)];  // per head: [k_nope(128) | v(128)]
__device__ float g_att[T_*NH_*VHD_];          // attention output [t][h*128+v]

// =====================================================================
// SGEMM: C[M,N] = A[M,K] * B[N,K]^T + bias[N]   (both K-contiguous)
// 128x128 tile, BK=16, 8x8 per thread, 256 threads.
// =====================================================================
__global__ __launch_bounds__(256, 2) void sgemm_nt_bias(
    const float* __restrict__ A, const float* __restrict__ B,
    const float* __restrict__ bias, float* __restrict__ C,
    int M, int N, int K)
{
    __shared__ float As[16][128];
    __shared__ float Bs[16][128];
    const int tid = threadIdx.x;
    const int tx  = tid & 15, ty = tid >> 4;
    const int bm  = blockIdx.y * 128, bn = blockIdx.x * 128;
    const int lr  = tid >> 1;         // 0..127 (row of the tile this thread loads)
    const int lk  = (tid & 1) * 8;    // 0 or 8 (k offset)

    const float* Ap = A + (size_t)(bm + lr) * K + lk;
    const int brow  = bn + lr;
    const float* Bp = B + (size_t)brow * K + lk;
    const bool bok  = (brow < N);

    float acc[8][8];
#pragma unroll
    for (int i = 0; i < 8; i++)
#pragma unroll
        for (int j = 0; j < 8; j++) acc[i][j] = 0.f;

    float4 a0 = *(const float4*)(Ap);
    float4 a1 = *(const float4*)(Ap + 4);
    float4 b0 = bok ? *(const float4*)(Bp)     : make_float4(0.f,0.f,0.f,0.f);
    float4 b1 = bok ? *(const float4*)(Bp + 4) : make_float4(0.f,0.f,0.f,0.f);

    for (int k0 = 0; k0 < K; k0 += 16) {
        // transpose-store current tile
        As[lk+0][lr]=a0.x; As[lk+1][lr]=a0.y; As[lk+2][lr]=a0.z; As[lk+3][lr]=a0.w;
        As[lk+4][lr]=a1.x; As[lk+5][lr]=a1.y; As[lk+6][lr]=a1.z; As[lk+7][lr]=a1.w;
        Bs[lk+0][lr]=b0.x; Bs[lk+1][lr]=b0.y; Bs[lk+2][lr]=b0.z; Bs[lk+3][lr]=b0.w;
        Bs[lk+4][lr]=b1.x; Bs[lk+5][lr]=b1.y; Bs[lk+6][lr]=b1.z; Bs[lk+7][lr]=b1.w;
        __syncthreads();

        // prefetch next tile into registers (latency hidden by compute)
        const int kn = k0 + 16;
        if (kn < K) {
            a0 = *(const float4*)(Ap + kn);
            a1 = *(const float4*)(Ap + kn + 4);
            if (bok) {
                b0 = *(const float4*)(Bp + kn);
                b1 = *(const float4*)(Bp + kn + 4);
            }
        }

#pragma unroll
        for (int kk = 0; kk < 16; kk++) {
            float ra[8], rb[8];
            *(float4*)&ra[0] = *(const float4*)&As[kk][ty*8];
            *(float4*)&ra[4] = *(const float4*)&As[kk][ty*8 + 4];
            *(float4*)&rb[0] = *(const float4*)&Bs[kk][tx*4];
            *(float4*)&rb[4] = *(const float4*)&Bs[kk][64 + tx*4];
#pragma unroll
            for (int i = 0; i < 8; i++)
#pragma unroll
                for (int j = 0; j < 8; j++)
                    acc[i][j] = fmaf(ra[i], rb[j], acc[i][j]);
        }
        __syncthreads();
    }

#pragma unroll
    for (int i = 0; i < 8; i++) {
        const int row = bm + ty*8 + i;
#pragma unroll
        for (int j = 0; j < 8; j++) {
            const int col = bn + ((j < 4) ? tx*4 + j : 64 + tx*4 + (j - 4));
            if (col < N) C[(size_t)row * N + col] = acc[i][j] + bias[col];
        }
    }
}

// =====================================================================
// RMSNorm over leading N elems of each row (strided in/out)
// =====================================================================
__global__ __launch_bounds__(256) void rmsnorm_kernel(
    const float* __restrict__ in, int ldin,
    const float* __restrict__ w,
    float* __restrict__ out, int ldout, int N)
{
    const float* x = in  + (size_t)blockIdx.x * ldin;
    float*       y = out + (size_t)blockIdx.x * ldout;
    float ss = 0.f;
    for (int i = threadIdx.x; i < N; i += 256) { float v = x[i]; ss = fmaf(v, v, ss); }
#pragma unroll
    for (int off = 16; off; off >>= 1) ss += __shfl_xor_sync(0xffffffffu, ss, off);
    __shared__ float red[8];
    __shared__ float s_inv;
    if ((threadIdx.x & 31) == 0) red[threadIdx.x >> 5] = ss;
    __syncthreads();
    if (threadIdx.x == 0) {
        float tot = 0.f;
#pragma unroll
        for (int k = 0; k < 8; k++) tot += red[k];
        s_inv = rsqrtf(tot / (float)N + 1e-6f);
    }
    __syncthreads();
    const float inv = s_inv;
    for (int i = threadIdx.x; i < N; i += 256) y[i] = x[i] * inv * w[i];
}

// =====================================================================
// RoPE (dim 64: pairs (i, 32+i), angle = pos * 10000^(-i/32))
// =====================================================================
#define L2_10K_DIV32 0.4152410118609203f   // log2(10000)/32

__global__ __launch_bounds__(256) void rope_q_kernel(float* __restrict__ q)
{
    const int idx = blockIdx.x * 256 + threadIdx.x;        // T*16*32 threads
    if (idx >= T_ * NH_ * 32) return;
    const int i = idx & 31;
    const int h = (idx >> 5) & 15;
    const int t = idx >> 9;
    const int pos = t & (SEQ_ - 1);
    const float invf = exp2f(-(float)i * L2_10K_DIV32);
    float s, c;
    sincosf((float)pos * invf, &s, &c);
    float* p = q + (size_t)t * (NH_*QKHD_) + h * QKHD_ + NOPE_;
    const float x1 = p[i], x2 = p[32 + i];
    p[i]      = x1 * c - x2 * s;
    p[32 + i] = x2 * c + x1 * s;
}

__global__ __launch_bounds__(256) void rope_k_kernel(float* __restrict__ kva)
{
    const int idx = blockIdx.x * 256 + threadIdx.x;        // T*32 threads
    if (idx >= T_ * 32) return;
    const int i = idx & 31;
    const int t = idx >> 5;
    const int pos = t & (SEQ_ - 1);
    const float invf = exp2f(-(float)i * L2_10K_DIV32);
    float s, c;
    sincosf((float)pos * invf, &s, &c);
    float* p = kva + (size_t)t * (KVLORA_+ROPE_) + KVLORA_;
    const float x1 = p[i], x2 = p[32 + i];
    p[i]      = x1 * c - x2 * s;
    p[32 + i] = x2 * c + x1 * s;
}

// =====================================================================
// Causal flash attention (fp32).
// Grid: (16 qtiles, 16 heads, 2 batch), 256 threads.
// Tile 128 q-rows x 128 k-cols; d streamed in chunks of 16 via smem.
// Q from g_q [t][h*192+d]; K = [kvb nope | kva rope]; V = kvb[..128..255].
// Online softmax, P->smem, PV GEMM. Out: g_att[t][h*128+v].
// =====================================================================
#define ATT_SMEM ((2*16*128 + 2*128*136) * 4)   // 155648 bytes

__global__ __launch_bounds__(256, 1) void mla_attn(
    const float* __restrict__ Qb, const float* __restrict__ KVb,
    const float* __restrict__ KVa, float* __restrict__ Ob)
{
    extern __shared__ float sm[];
    float* Qs = sm;                    // [16][128]
    float* Ks = sm + 16*128;           // [16][128]
    float* Vs = sm + 2*16*128;         // [128][136]
    float* Ps = Vs + 128*136;          // [128][136]

    const int qt  = (int)gridDim.x - 1 - (int)blockIdx.x;  // longest tiles first
    const int h   = blockIdx.y, b = blockIdx.z;
    const int tid = threadIdx.x, tx = tid & 15, ty = tid >> 4;
    const int rowBase = ty * 8;
    const int lr  = tid >> 1;          // 0..127
    const int q_t0 = b * SEQ_ + qt * 128;
    const float scale = 0.07216878364870323f;   // 1/sqrt(192)

    float accO[8][8];
    float m[8], l[8];
#pragma unroll
    for (int i = 0; i < 8; i++) {
        m[i] = -1e30f; l[i] = 0.f;
#pragma unroll
        for (int j = 0; j < 8; j++) accO[i][j] = 0.f;
    }

    for (int kt = 0; kt <= qt; ++kt) {
        const int k_t0 = b * SEQ_ + kt * 128;

        // ---- load V tile [128 tokens][128 dims] ----
        {
            const int c0 = (tid & 1) * 64;
            const float4* src = (const float4*)(KVb + (size_t)(k_t0 + lr) * 4096 + h * 256 + 128 + c0);
            float4* dst = (float4*)(Vs + lr * 136 + c0);
#pragma unroll
            for (int q4 = 0; q4 < 16; ++q4) dst[q4] = src[q4];
        }

        // ---- scores S = Q K^T over d=192, chunks of 16 ----
        float acc[8][8];
#pragma unroll
        for (int i = 0; i < 8; i++)
#pragma unroll
            for (int j = 0; j < 8; j++) acc[i][j] = 0.f;

        for (int dc = 0; dc < QKHD_; dc += 16) {
            const int k8 = (tid & 1) * 8;
            const int d  = dc + k8;
            const float* qp = Qb + (size_t)(q_t0 + lr) * (NH_*QKHD_) + h * QKHD_ + d;
            float4 q0 = *(const float4*)(qp);
            float4 q1 = *(const float4*)(qp + 4);
            const float* kp = (d < NOPE_)
                ? (KVb + (size_t)(k_t0 + lr) * 4096 + h * 256 + d)
                : (KVa + (size_t)(k_t0 + lr) * (KVLORA_+ROPE_) + KVLORA_ + (d - NOPE_));
            float4 kv0 = *(const float4*)(kp);
            float4 kv1 = *(const float4*)(kp + 4);
            __syncthreads();   // previous chunk's compute done
            Qs[(k8+0)*128+lr]=q0.x;  Qs[(k8+1)*128+lr]=q0.y;  Qs[(k8+2)*128+lr]=q0.z;  Qs[(k8+3)*128+lr]=q0.w;
            Qs[(k8+4)*128+lr]=q1.x;  Qs[(k8+5)*128+lr]=q1.y;  Qs[(k8+6)*128+lr]=q1.z;  Qs[(k8+7)*128+lr]=q1.w;
            Ks[(k8+0)*128+lr]=kv0.x; Ks[(k8+1)*128+lr]=kv0.y; Ks[(k8+2)*128+lr]=kv0.z; Ks[(k8+3)*128+lr]=kv0.w;
            Ks[(k8+4)*128+lr]=kv1.x; Ks[(k8+5)*128+lr]=kv1.y; Ks[(k8+6)*128+lr]=kv1.z; Ks[(k8+7)*128+lr]=kv1.w;
            __syncthreads();
#pragma unroll
            for (int kk = 0; kk < 16; kk++) {
                float rq[8], rk[8];
                *(float4*)&rq[0] = *(const float4*)&Qs[kk*128 + rowBase];
                *(float4*)&rq[4] = *(const float4*)&Qs[kk*128 + rowBase + 4];
                *(float4*)&rk[0] = *(const float4*)&Ks[kk*128 + tx*4];
                *(float4*)&rk[4] = *(const float4*)&Ks[kk*128 + 64 + tx*4];
#pragma unroll
                for (int i = 0; i < 8; i++)
#pragma unroll
                    for (int j = 0; j < 8; j++)
                        acc[i][j] = fmaf(rq[i], rk[j], acc[i][j]);
            }
        }

        // ---- scale + causal mask + online softmax ----
#pragma unroll
        for (int i = 0; i < 8; i++) {
            const int rglob = qt*128 + rowBase + i;
            float tmax = -1e30f;
#pragma unroll
            for (int j = 0; j < 8; j++) {
                const int cglob = kt*128 + ((j < 4) ? tx*4 + j : 64 + tx*4 + (j - 4));
                float s = acc[i][j] * scale;
                s = (cglob > rglob) ? -1e30f : s;
                acc[i][j] = s;
                tmax = fmaxf(tmax, s);
            }
#pragma unroll
            for (int off = 8; off; off >>= 1)
                tmax = fmaxf(tmax, __shfl_xor_sync(0xffffffffu, tmax, off));
            const float mn   = fmaxf(m[i], tmax);
            const float corr = __expf(m[i] - mn);
            l[i] *= corr;
#pragma unroll
            for (int j = 0; j < 8; j++) accO[i][j] *= corr;
            float rs = 0.f;
#pragma unroll
            for (int j = 0; j < 8; j++) {
                const float p = __expf(acc[i][j] - mn);
                acc[i][j] = p;
                rs += p;
            }
#pragma unroll
            for (int off = 8; off; off >>= 1)
                rs += __shfl_xor_sync(0xffffffffu, rs, off);
            l[i] += rs;
            m[i]  = mn;
            *(float4*)&Ps[(rowBase + i)*136 + tx*4]      = *(float4*)&acc[i][0];
            *(float4*)&Ps[(rowBase + i)*136 + 64 + tx*4] = *(float4*)&acc[i][4];
        }
        __syncthreads();   // P + V visible

        // ---- O += P * V ----
#pragma unroll 4
        for (int c = 0; c < 128; c++) {
            float rv[8], rp[8];
            *(float4*)&rv[0] = *(const float4*)&Vs[c*136 + tx*4];
            *(float4*)&rv[4] = *(const float4*)&Vs[c*136 + 64 + tx*4];
#pragma unroll
            for (int i = 0; i < 8; i++) rp[i] = Ps[(rowBase + i)*136 + c];
#pragma unroll
            for (int i = 0; i < 8; i++)
#pragma unroll
                for (int j = 0; j < 8; j++)
                    accO[i][j] = fmaf(rp[i], rv[j], accO[i][j]);
        }
        __syncthreads();   // before next tile overwrites Vs/Ps
    }

    // ---- epilogue: O/l -> g_att[t][h*128+v] ----
#pragma unroll
    for (int i = 0; i < 8; i++) {
        const float inv = 1.f / l[i];
        const size_t row = (size_t)(q_t0 + rowBase + i);
#pragma unroll
        for (int j = 0; j < 8; j++) {
            const int col = h*128 + ((j < 4) ? tx*4 + j : 64 + tx*4 + (j - 4));
            Ob[row * (NH_*VHD_) + col] = accO[i][j] * inv;
        }
    }
}

// =====================================================================
// launch
// =====================================================================
extern "C" void kernel_launch(void* const* d_in, const int* in_sizes, int n_in,
                              void* d_out, int out_size)
{
    const float* x      = (const float*)d_in[0];
    const float* wqa    = (const float*)d_in[1];
    const float* wqa_b  = (const float*)d_in[2];
    const float* qnw    = (const float*)d_in[3];
    const float* wqb    = (const float*)d_in[4];
    const float* wqb_b  = (const float*)d_in[5];
    const float* wkva   = (const float*)d_in[6];
    const float* wkva_b = (const float*)d_in[7];
    const float* kvnw   = (const float*)d_in[8];
    const float* wkvb   = (const float*)d_in[9];
    const float* wkvb_b = (const float*)d_in[10];
    const float* wo     = (const float*)d_in[11];
    const float* wo_b   = (const float*)d_in[12];
    float* out = (float*)d_out;

    float *p_qa, *p_q, *p_kva, *p_kvn, *p_kvb, *p_att;
    cudaGetSymbolAddress((void**)&p_qa,  g_qa);
    cudaGetSymbolAddress((void**)&p_q,   g_q);
    cudaGetSymbolAddress((void**)&p_kva, g_kva);
    cudaGetSymbolAddress((void**)&p_kvn, g_kvn);
    cudaGetSymbolAddress((void**)&p_kvb, g_kvb);
    cudaGetSymbolAddress((void**)&p_att, g_att);

    cudaFuncSetAttribute(mla_attn, cudaFuncAttributeMaxDynamicSharedMemorySize, ATT_SMEM);

    const dim3 blk(256);
    const int mt = T_ / 128;  // 32

    // Q path
    sgemm_nt_bias<<<dim3(QLORA_/128, mt), blk>>>(x, wqa, wqa_b, p_qa, T_, QLORA_, DIM_);
    rmsnorm_kernel<<<T_, blk>>>(p_qa, QLORA_, qnw, p_qa, QLORA_, QLORA_);
    sgemm_nt_bias<<<dim3((NH_*QKHD_)/128, mt), blk>>>(p_qa, wqb, wqb_b, p_q, T_, NH_*QKHD_, QLORA_);
    rope_q_kernel<<<(T_*NH_*32)/256, blk>>>(p_q);

    // KV path
    sgemm_nt_bias<<<dim3((KVLORA_+ROPE_+127)/128, mt), blk>>>(x, wkva, wkva_b, p_kva, T_, KVLORA_+ROPE_, DIM_);
    rope_k_kernel<<<(T_*32)/256, blk>>>(p_kva);
    rmsnorm_kernel<<<T_, blk>>>(p_kva, KVLORA_+ROPE_, kvnw, p_kvn, KVLORA_, KVLORA_);
    sgemm_nt_bias<<<dim3((NH_*(NOPE_+VHD_))/128, mt), blk>>>(p_kvn, wkvb, wkvb_b, p_kvb, T_, NH_*(NOPE_+VHD_), KVLORA_);

    // Attention
    mla_attn<<<dim3(SEQ_/128, NH_, BS_), blk, ATT_SMEM>>>(p_q, p_kvb, p_kva, p_att);

    // Output projection
    sgemm_nt_bias<<<dim3(DIM_/128, mt), blk>>>(p_att, wo, wo_b, out, T_, DIM_, NH_*VHD_);
}

// round 11
// speedup vs baseline: 2.0159x; 2.0159x over previous
#include <cuda_runtime.h>
#include <cuda_bf16.h>
#include <math.h>
#include <stdint.h>

// ---------------- problem constants ----------------
#define BS_     2
#define SEQ_    2048
#define T_      (BS_*SEQ_)      // 4096 tokens
#define DIM_    2048
#define NH_     16
#define QLORA_  1536
#define KVLORA_ 512
#define NOPE_   128
#define ROPE_   64
#define QKHD_   192             // NOPE+ROPE
#define VHD_    128

// ---------------- scratch (static device globals; no runtime alloc) ----------------
__device__ float g_qa [T_*QLORA_];            // qa GEMM out; rmsnorm writes tf32-rounded in place
__device__ float g_q  [T_*NH_*QKHD_];         // q after b-proj (+rope), fp32
__device__ float g_kva[T_*(KVLORA_+ROPE_)];   // kv_a out; last 64 = k_pe (+rope), fp32
__device__ float g_kvn[T_*KVLORA_];           // rmsnorm(kv_c), tf32-rounded
__device__ float g_kvb[T_*NH_*(NOPE_+VHD_)];  // per head: [k_nope(128) | v(128)], fp32
__device__ float g_att[T_*NH_*VHD_];          // attention out, tf32-rounded

// tf32-rounded copies of GEMM operands
__device__ float g_xt   [T_*DIM_];
__device__ float g_wqat [QLORA_*DIM_];
__device__ float g_wqbt [NH_*QKHD_*QLORA_];
__device__ float g_wkvat[(KVLORA_+ROPE_)*DIM_];
__device__ float g_wkvbt[NH_*(NOPE_+VHD_)*KVLORA_];
__device__ float g_wot  [DIM_*NH_*VHD_];

// =====================================================================
// helpers
// =====================================================================
__device__ __forceinline__ uint32_t tf32r(float x) {
    uint32_t u;
    asm("cvt.rna.tf32.f32 %0, %1;" : "=r"(u) : "f"(x));
    return u;
}
__device__ __forceinline__ float tf32rf(float x) { return __uint_as_float(tf32r(x)); }

__device__ __forceinline__ void cpa16(uint32_t d, const void* g) {
    asm volatile("cp.async.cg.shared.global [%0], [%1], 16;" :: "r"(d), "l"(g));
}
__device__ __forceinline__ void cpa16z(uint32_t d, const void* g, int sz) {
    asm volatile("cp.async.cg.shared.global [%0], [%1], 16, %2;" :: "r"(d), "l"(g), "r"(sz));
}

__device__ __forceinline__ void mma_tf32(float* c, const uint32_t* a, const uint32_t* b) {
    asm volatile(
        "mma.sync.aligned.m16n8k8.row.col.f32.tf32.tf32.f32 "
        "{%0,%1,%2,%3}, {%4,%5,%6,%7}, {%8,%9}, {%0,%1,%2,%3};\n"
        : "+f"(c[0]), "+f"(c[1]), "+f"(c[2]), "+f"(c[3])
        : "r"(a[0]), "r"(a[1]), "r"(a[2]), "r"(a[3]), "r"(b[0]), "r"(b[1]));
}

// =====================================================================
// elementwise tf32 round
// =====================================================================
__global__ __launch_bounds__(256) void cvt_tf32(const float* __restrict__ in,
                                                float* __restrict__ out, int n)
{
    const int i = (blockIdx.x * 256 + threadIdx.x) * 4;
    if (i >= n) return;
    float4 v = *(const float4*)(in + i);
    v.x = tf32rf(v.x); v.y = tf32rf(v.y); v.z = tf32rf(v.z); v.w = tf32rf(v.w);
    *(float4*)(out + i) = v;
}

// =====================================================================
// tf32 mma.sync GEMM: C[M,N] = A[M,K] * B[N,K]^T + bias[N]
// Operands MUST be pre-rounded to tf32 (HW truncation is then exact).
// CTA 128x128, BK=32, 3-stage cp.async, 8 warps (warp tile 64x32).
// Smem layout per tile: row-major, 128B/row, SW128 XOR swizzle.
// =====================================================================
#define GSTAGE 32768
#define GSM    (3*GSTAGE)

__device__ __forceinline__ void g_load_stage(
    const float* __restrict__ A, const float* __restrict__ B,
    int N, int K, int bm, int bn, int k0,
    uint32_t sA, uint32_t sB, int tid)
{
#pragma unroll
    for (int i = 0; i < 4; ++i) {
        const int c = tid + i * 256;        // 0..1023
        const int row = c >> 3, j = c & 7;  // row 0..127, 16B chunk 0..7
        const uint32_t soff = (uint32_t)(row * 128 + ((j ^ (row & 7)) << 4));
        cpa16(sA + soff, A + (size_t)(bm + row) * K + k0 + j * 4);
        const int gr = bn + row;
        const bool ok = gr < N;
        cpa16z(sB + soff, B + (size_t)(ok ? gr : 0) * K + k0 + j * 4, ok ? 16 : 0);
    }
}

__global__ __launch_bounds__(256, 2) void gemm_mma(
    const float* __restrict__ A, const float* __restrict__ B,
    const float* __restrict__ bias, float* __restrict__ C,
    int M, int N, int K)
{
    extern __shared__ __align__(128) char smg[];
    const uint32_t sb = (uint32_t)__cvta_generic_to_shared(smg);
    const int tid = threadIdx.x, lane = tid & 31, w = tid >> 5;
    const int wm = w & 1, wn = w >> 1;          // 2 x 4 warp grid
    const int bm = blockIdx.y * 128, bn = blockIdx.x * 128;

    float acc[4][4][4];
#pragma unroll
    for (int mi = 0; mi < 4; ++mi)
#pragma unroll
        for (int nj = 0; nj < 4; ++nj)
#pragma unroll
            for (int r = 0; r < 4; ++r) acc[mi][nj][r] = 0.f;

    const int nk = K >> 5;

    // prologue: stages 0,1
#pragma unroll
    for (int s = 0; s < 2; ++s) {
        g_load_stage(A, B, N, K, bm, bn, s * 32, sb + s * GSTAGE, sb + s * GSTAGE + 16384, tid);
        asm volatile("cp.async.commit_group;" ::: "memory");
    }

    for (int t = 0; t < nk; ++t) {
        asm volatile("cp.async.wait_group 1;" ::: "memory");
        __syncthreads();

        const int tn = t + 2;
        if (tn < nk) {
            const uint32_t so = sb + (uint32_t)(tn % 3) * GSTAGE;
            g_load_stage(A, B, N, K, bm, bn, tn * 32, so, so + 16384, tid);
        }
        asm volatile("cp.async.commit_group;" ::: "memory");

        const uint32_t sA = sb + (uint32_t)(t % 3) * GSTAGE;
        const uint32_t sB = sA + 16384;

#pragma unroll
        for (int ks = 0; ks < 4; ++ks) {
            uint32_t af[4][4];
#pragma unroll
            for (int mi = 0; mi < 4; ++mi) {
                const int mat = lane >> 3;
                const int row = wm * 64 + mi * 16 + (lane & 7) + ((mat & 1) << 3);
                const int chunk = 2 * ks + (mat >> 1);
                const uint32_t ad = sA + (uint32_t)(row * 128 + ((chunk ^ (row & 7)) << 4));
                asm volatile("ldmatrix.sync.aligned.m8n8.x4.shared.b16 {%0,%1,%2,%3}, [%4];"
                             : "=r"(af[mi][0]), "=r"(af[mi][1]), "=r"(af[mi][2]), "=r"(af[mi][3])
                             : "r"(ad));
            }
            uint32_t bf[4][2];
#pragma unroll
            for (int nj = 0; nj < 4; ++nj) {
                const int n  = wn * 32 + nj * 8 + (lane >> 2);
                const int kk = ks * 8 + (lane & 3);
                const uint32_t b0a = sB + (uint32_t)(n * 128 + (((2*ks)   ^ (n & 7)) << 4) + ((kk & 3) << 2));
                const uint32_t b1a = sB + (uint32_t)(n * 128 + (((2*ks+1) ^ (n & 7)) << 4) + ((kk & 3) << 2));
                asm volatile("ld.shared.b32 %0, [%1];" : "=r"(bf[nj][0]) : "r"(b0a));
                asm volatile("ld.shared.b32 %0, [%1];" : "=r"(bf[nj][1]) : "r"(b1a));
            }
#pragma unroll
            for (int mi = 0; mi < 4; ++mi)
#pragma unroll
                for (int nj = 0; nj < 4; ++nj)
                    mma_tf32(acc[mi][nj], af[mi], bf[nj]);
        }
    }

    // epilogue: C = acc + bias
#pragma unroll
    for (int mi = 0; mi < 4; ++mi) {
        const int r0 = bm + wm * 64 + mi * 16 + (lane >> 2);
#pragma unroll
        for (int nj = 0; nj < 4; ++nj) {
            const int c0 = bn + wn * 32 + nj * 8 + ((lane & 3) << 1);
            if (c0 < N) {
                const float b0 = bias[c0], b1 = bias[c0 + 1];
                float2 v0 = make_float2(acc[mi][nj][0] + b0, acc[mi][nj][1] + b1);
                float2 v1 = make_float2(acc[mi][nj][2] + b0, acc[mi][nj][3] + b1);
                *(float2*)(C + (size_t)r0 * N + c0)       = v0;
                *(float2*)(C + (size_t)(r0 + 8) * N + c0) = v1;
            }
        }
    }
}

// =====================================================================
// RMSNorm (emits tf32-rounded output: next consumer is a tf32 GEMM)
// =====================================================================
__global__ __launch_bounds__(256) void rmsnorm_kernel(
    const float* __restrict__ in, int ldin,
    const float* __restrict__ w,
    float* __restrict__ out, int ldout, int N)
{
    const float* x = in  + (size_t)blockIdx.x * ldin;
    float*       y = out + (size_t)blockIdx.x * ldout;
    float ss = 0.f;
    for (int i = threadIdx.x; i < N; i += 256) { float v = x[i]; ss = fmaf(v, v, ss); }
#pragma unroll
    for (int off = 16; off; off >>= 1) ss += __shfl_xor_sync(0xffffffffu, ss, off);
    __shared__ float red[8];
    __shared__ float s_inv;
    if ((threadIdx.x & 31) == 0) red[threadIdx.x >> 5] = ss;
    __syncthreads();
    if (threadIdx.x == 0) {
        float tot = 0.f;
#pragma unroll
        for (int k = 0; k < 8; k++) tot += red[k];
        s_inv = rsqrtf(tot / (float)N + 1e-6f);
    }
    __syncthreads();
    const float inv = s_inv;
    for (int i = threadIdx.x; i < N; i += 256) y[i] = tf32rf(x[i] * inv * w[i]);
}

// =====================================================================
// RoPE
// =====================================================================
#define L2_10K_DIV32 0.4152410118609203f

__global__ __launch_bounds__(256) void rope_q_kernel(float* __restrict__ q)
{
    const int idx = blockIdx.x * 256 + threadIdx.x;
    if (idx >= T_ * NH_ * 32) return;
    const int i = idx & 31;
    const int h = (idx >> 5) & 15;
    const int t = idx >> 9;
    const int pos = t & (SEQ_ - 1);
    const float invf = exp2f(-(float)i * L2_10K_DIV32);
    float s, c;
    sincosf((float)pos * invf, &s, &c);
    float* p = q + (size_t)t * (NH_*QKHD_) + h * QKHD_ + NOPE_;
    const float x1 = p[i], x2 = p[32 + i];
    p[i]      = x1 * c - x2 * s;
    p[32 + i] = x2 * c + x1 * s;
}

__global__ __launch_bounds__(256) void rope_k_kernel(float* __restrict__ kva)
{
    const int idx = blockIdx.x * 256 + threadIdx.x;
    if (idx >= T_ * 32) return;
    const int i = idx & 31;
    const int t = idx >> 5;
    const int pos = t & (SEQ_ - 1);
    const float invf = exp2f(-(float)i * L2_10K_DIV32);
    float s, c;
    sincosf((float)pos * invf, &s, &c);
    float* p = kva + (size_t)t * (KVLORA_+ROPE_) + KVLORA_;
    const float x1 = p[i], x2 = p[32 + i];
    p[i]      = x1 * c - x2 * s;
    p[32 + i] = x2 * c + x1 * s;
}

// =====================================================================
// Causal flash attention (fp32) — proven R5 kernel; epilogue now emits
// tf32-rounded output for the o-projection GEMM.
// =====================================================================
#define ATT_SMEM ((2*16*128 + 2*128*136) * 4)

__global__ __launch_bounds__(256, 1) void mla_attn(
    const float* __restrict__ Qb, const float* __restrict__ KVb,
    const float* __restrict__ KVa, float* __restrict__ Ob)
{
    extern __shared__ float sm[];
    float* Qs = sm;
    float* Ks = sm + 16*128;
    float* Vs = sm + 2*16*128;
    float* Ps = Vs + 128*136;

    const int qt  = (int)gridDim.x - 1 - (int)blockIdx.x;
    const int h   = blockIdx.y, b = blockIdx.z;
    const int tid = threadIdx.x, tx = tid & 15, ty = tid >> 4;
    const int rowBase = ty * 8;
    const int lr  = tid >> 1;
    const int q_t0 = b * SEQ_ + qt * 128;
    const float scale = 0.07216878364870323f;

    float accO[8][8];
    float m[8], l[8];
#pragma unroll
    for (int i = 0; i < 8; i++) {
        m[i] = -1e30f; l[i] = 0.f;
#pragma unroll
        for (int j = 0; j < 8; j++) accO[i][j] = 0.f;
    }

    for (int kt = 0; kt <= qt; ++kt) {
        const int k_t0 = b * SEQ_ + kt * 128;

        {
            const int c0 = (tid & 1) * 64;
            const float4* src = (const float4*)(KVb + (size_t)(k_t0 + lr) * 4096 + h * 256 + 128 + c0);
            float4* dst = (float4*)(Vs + lr * 136 + c0);
#pragma unroll
            for (int q4 = 0; q4 < 16; ++q4) dst[q4] = src[q4];
        }

        float acc[8][8];
#pragma unroll
        for (int i = 0; i < 8; i++)
#pragma unroll
            for (int j = 0; j < 8; j++) acc[i][j] = 0.f;

        for (int dc = 0; dc < QKHD_; dc += 16) {
            const int k8 = (tid & 1) * 8;
            const int d  = dc + k8;
            const float* qp = Qb + (size_t)(q_t0 + lr) * (NH_*QKHD_) + h * QKHD_ + d;
            float4 q0 = *(const float4*)(qp);
            float4 q1 = *(const float4*)(qp + 4);
            const float* kp = (d < NOPE_)
                ? (KVb + (size_t)(k_t0 + lr) * 4096 + h * 256 + d)
                : (KVa + (size_t)(k_t0 + lr) * (KVLORA_+ROPE_) + KVLORA_ + (d - NOPE_));
            float4 kv0 = *(const float4*)(kp);
            float4 kv1 = *(const float4*)(kp + 4);
            __syncthreads();
            Qs[(k8+0)*128+lr]=q0.x;  Qs[(k8+1)*128+lr]=q0.y;  Qs[(k8+2)*128+lr]=q0.z;  Qs[(k8+3)*128+lr]=q0.w;
            Qs[(k8+4)*128+lr]=q1.x;  Qs[(k8+5)*128+lr]=q1.y;  Qs[(k8+6)*128+lr]=q1.z;  Qs[(k8+7)*128+lr]=q1.w;
            Ks[(k8+0)*128+lr]=kv0.x; Ks[(k8+1)*128+lr]=kv0.y; Ks[(k8+2)*128+lr]=kv0.z; Ks[(k8+3)*128+lr]=kv0.w;
            Ks[(k8+4)*128+lr]=kv1.x; Ks[(k8+5)*128+lr]=kv1.y; Ks[(k8+6)*128+lr]=kv1.z; Ks[(k8+7)*128+lr]=kv1.w;
            __syncthreads();
#pragma unroll
            for (int kk = 0; kk < 16; kk++) {
                float rq[8], rk[8];
                *(float4*)&rq[0] = *(const float4*)&Qs[kk*128 + rowBase];
                *(float4*)&rq[4] = *(const float4*)&Qs[kk*128 + rowBase + 4];
                *(float4*)&rk[0] = *(const float4*)&Ks[kk*128 + tx*4];
                *(float4*)&rk[4] = *(const float4*)&Ks[kk*128 + 64 + tx*4];
#pragma unroll
                for (int i = 0; i < 8; i++)
#pragma unroll
                    for (int j = 0; j < 8; j++)
                        acc[i][j] = fmaf(rq[i], rk[j], acc[i][j]);
            }
        }

#pragma unroll
        for (int i = 0; i < 8; i++) {
            const int rglob = qt*128 + rowBase + i;
            float tmax = -1e30f;
#pragma unroll
            for (int j = 0; j < 8; j++) {
                const int cglob = kt*128 + ((j < 4) ? tx*4 + j : 64 + tx*4 + (j - 4));
                float s = acc[i][j] * scale;
                s = (cglob > rglob) ? -1e30f : s;
                acc[i][j] = s;
                tmax = fmaxf(tmax, s);
            }
#pragma unroll
            for (int off = 8; off; off >>= 1)
                tmax = fmaxf(tmax, __shfl_xor_sync(0xffffffffu, tmax, off));
            const float mn   = fmaxf(m[i], tmax);
            const float corr = __expf(m[i] - mn);
            l[i] *= corr;
#pragma unroll
            for (int j = 0; j < 8; j++) accO[i][j] *= corr;
            float rs = 0.f;
#pragma unroll
            for (int j = 0; j < 8; j++) {
                const float p = __expf(acc[i][j] - mn);
                acc[i][j] = p;
                rs += p;
            }
#pragma unroll
            for (int off = 8; off; off >>= 1)
                rs += __shfl_xor_sync(0xffffffffu, rs, off);
            l[i] += rs;
            m[i]  = mn;
            *(float4*)&Ps[(rowBase + i)*136 + tx*4]      = *(float4*)&acc[i][0];
            *(float4*)&Ps[(rowBase + i)*136 + 64 + tx*4] = *(float4*)&acc[i][4];
        }
        __syncthreads();

#pragma unroll 4
        for (int c = 0; c < 128; c++) {
            float rv[8], rp[8];
            *(float4*)&rv[0] = *(const float4*)&Vs[c*136 + tx*4];
            *(float4*)&rv[4] = *(const float4*)&Vs[c*136 + 64 + tx*4];
#pragma unroll
            for (int i = 0; i < 8; i++) rp[i] = Ps[(rowBase + i)*136 + c];
#pragma unroll
            for (int i = 0; i < 8; i++)
#pragma unroll
                for (int j = 0; j < 8; j++)
                    accO[i][j] = fmaf(rp[i], rv[j], accO[i][j]);
        }
        __syncthreads();
    }

#pragma unroll
    for (int i = 0; i < 8; i++) {
        const float inv = 1.f / l[i];
        const size_t row = (size_t)(q_t0 + rowBase + i);
#pragma unroll
        for (int j = 0; j < 8; j++) {
            const int col = h*128 + ((j < 4) ? tx*4 + j : 64 + tx*4 + (j - 4));
            Ob[row * (NH_*VHD_) + col] = tf32rf(accO[i][j] * inv);
        }
    }
}

// =====================================================================
// launch
// =====================================================================
extern "C" void kernel_launch(void* const* d_in, const int* in_sizes, int n_in,
                              void* d_out, int out_size)
{
    const float* x      = (const float*)d_in[0];
    const float* wqa    = (const float*)d_in[1];
    const float* wqa_b  = (const float*)d_in[2];
    const float* qnw    = (const float*)d_in[3];
    const float* wqb    = (const float*)d_in[4];
    const float* wqb_b  = (const float*)d_in[5];
    const float* wkva   = (const float*)d_in[6];
    const float* wkva_b = (const float*)d_in[7];
    const float* kvnw   = (const float*)d_in[8];
    const float* wkvb   = (const float*)d_in[9];
    const float* wkvb_b = (const float*)d_in[10];
    const float* wo     = (const float*)d_in[11];
    const float* wo_b   = (const float*)d_in[12];
    float* out = (float*)d_out;

    float *p_qa, *p_q, *p_kva, *p_kvn, *p_kvb, *p_att;
    float *p_xt, *p_wqat, *p_wqbt, *p_wkvat, *p_wkvbt, *p_wot;
    cudaGetSymbolAddress((void**)&p_qa,   g_qa);
    cudaGetSymbolAddress((void**)&p_q,    g_q);
    cudaGetSymbolAddress((void**)&p_kva,  g_kva);
    cudaGetSymbolAddress((void**)&p_kvn,  g_kvn);
    cudaGetSymbolAddress((void**)&p_kvb,  g_kvb);
    cudaGetSymbolAddress((void**)&p_att,  g_att);
    cudaGetSymbolAddress((void**)&p_xt,   g_xt);
    cudaGetSymbolAddress((void**)&p_wqat, g_wqat);
    cudaGetSymbolAddress((void**)&p_wqbt, g_wqbt);
    cudaGetSymbolAddress((void**)&p_wkvat,g_wkvat);
    cudaGetSymbolAddress((void**)&p_wkvbt,g_wkvbt);
    cudaGetSymbolAddress((void**)&p_wot,  g_wot);

    cudaFuncSetAttribute(gemm_mma, cudaFuncAttributeMaxDynamicSharedMemorySize, GSM);
    cudaFuncSetAttribute(mla_attn, cudaFuncAttributeMaxDynamicSharedMemorySize, ATT_SMEM);

    const dim3 blk256(256);
    const int mt = T_ / 128;  // 32

    // pre-round operands to tf32 (rna) so mma's truncation is exact
    cvt_tf32<<<(T_*DIM_)/1024, blk256>>>(x,    p_xt,    T_*DIM_);
    cvt_tf32<<<(QLORA_*DIM_)/1024, blk256>>>(wqa,  p_wqat,  QLORA_*DIM_);
    cvt_tf32<<<(NH_*QKHD_*QLORA_)/1024, blk256>>>(wqb,  p_wqbt,  NH_*QKHD_*QLORA_);
    cvt_tf32<<<((KVLORA_+ROPE_)*DIM_)/1024, blk256>>>(wkva, p_wkvat, (KVLORA_+ROPE_)*DIM_);
    cvt_tf32<<<(NH_*(NOPE_+VHD_)*KVLORA_)/1024, blk256>>>(wkvb, p_wkvbt, NH_*(NOPE_+VHD_)*KVLORA_);
    cvt_tf32<<<(DIM_*NH_*VHD_)/1024, blk256>>>(wo,   p_wot,   DIM_*NH_*VHD_);

    // Q path
    gemm_mma<<<dim3(QLORA_/128, mt), blk256, GSM>>>(p_xt, p_wqat, wqa_b, p_qa, T_, QLORA_, DIM_);
    rmsnorm_kernel<<<T_, blk256>>>(p_qa, QLORA_, qnw, p_qa, QLORA_, QLORA_);
    gemm_mma<<<dim3((NH_*QKHD_)/128, mt), blk256, GSM>>>(p_qa, p_wqbt, wqb_b, p_q, T_, NH_*QKHD_, QLORA_);
    rope_q_kernel<<<(T_*NH_*32)/256, blk256>>>(p_q);

    // KV path
    gemm_mma<<<dim3((KVLORA_+ROPE_+127)/128, mt), blk256, GSM>>>(p_xt, p_wkvat, wkva_b, p_kva, T_, KVLORA_+ROPE_, DIM_);
    rope_k_kernel<<<(T_*32)/256, blk256>>>(p_kva);
    rmsnorm_kernel<<<T_, blk256>>>(p_kva, KVLORA_+ROPE_, kvnw, p_kvn, KVLORA_, KVLORA_);
    gemm_mma<<<dim3((NH_*(NOPE_+VHD_))/128, mt), blk256, GSM>>>(p_kvn, p_wkvbt, wkvb_b, p_kvb, T_, NH_*(NOPE_+VHD_), KVLORA_);

    // Attention (fp32; emits tf32-rounded output)
    mla_attn<<<dim3(SEQ_/128, NH_, BS_), blk256, ATT_SMEM>>>(p_q, p_kvb, p_kva, p_att);

    // Output projection
    gemm_mma<<<dim3(DIM_/128, mt), blk256, GSM>>>(p_att, p_wot, wo_b, out, T_, DIM_, NH_*VHD_);
}

// round 14
// speedup vs baseline: 3.5757x; 1.7738x over previous
#include <cuda_runtime.h>
#include <cuda_bf16.h>
#include <math.h>
#include <stdint.h>

// ---------------- problem constants ----------------
#define BS_     2
#define SEQ_    2048
#define T_      (BS_*SEQ_)      // 4096 tokens
#define DIM_    2048
#define NH_     16
#define QLORA_  1536
#define KVLORA_ 512
#define NOPE_   128
#define ROPE_   64
#define QKHD_   192             // NOPE+ROPE
#define VHD_    128

// ---------------- scratch (static device globals; no runtime alloc) ----------------
__device__ float g_qa [T_*QLORA_];
__device__ float g_q  [T_*NH_*QKHD_];
__device__ float g_kva[T_*(KVLORA_+ROPE_)];
__device__ float g_kvn[T_*KVLORA_];
__device__ float g_kvb[T_*NH_*(NOPE_+VHD_)];
__device__ float g_att[T_*NH_*VHD_];

// tf32-rounded copies of GEMM operands
__device__ float g_xt   [T_*DIM_];
__device__ float g_wqat [QLORA_*DIM_];
__device__ float g_wqbt [NH_*QKHD_*QLORA_];
__device__ float g_wkvat[(KVLORA_+ROPE_)*DIM_];
__device__ float g_wkvbt[NH_*(NOPE_+VHD_)*KVLORA_];
__device__ float g_wot  [DIM_*NH_*VHD_];

// =====================================================================
// helpers
// =====================================================================
__device__ __forceinline__ uint32_t tf32r(float x) {
    uint32_t u;
    asm("cvt.rna.tf32.f32 %0, %1;" : "=r"(u) : "f"(x));
    return u;
}
__device__ __forceinline__ float tf32rf(float x) { return __uint_as_float(tf32r(x)); }

__device__ __forceinline__ void cpa16(uint32_t d, const void* g) {
    asm volatile("cp.async.cg.shared.global [%0], [%1], 16;" :: "r"(d), "l"(g));
}
__device__ __forceinline__ void cpa16z(uint32_t d, const void* g, int sz) {
    asm volatile("cp.async.cg.shared.global [%0], [%1], 16, %2;" :: "r"(d), "l"(g), "r"(sz));
}

__device__ __forceinline__ void mma_tf32(float* c, const uint32_t* a, const uint32_t* b) {
    asm volatile(
        "mma.sync.aligned.m16n8k8.row.col.f32.tf32.tf32.f32 "
        "{%0,%1,%2,%3}, {%4,%5,%6,%7}, {%8,%9}, {%0,%1,%2,%3};\n"
        : "+f"(c[0]), "+f"(c[1]), "+f"(c[2]), "+f"(c[3])
        : "r"(a[0]), "r"(a[1]), "r"(a[2]), "r"(a[3]), "r"(b[0]), "r"(b[1]));
}

#define LDMX4(af, addr) \
    asm volatile("ldmatrix.sync.aligned.m8n8.x4.shared.b16 {%0,%1,%2,%3}, [%4];" \
                 : "=r"((af)[0]), "=r"((af)[1]), "=r"((af)[2]), "=r"((af)[3]) : "r"(addr))

#define LDS32(r, addr) \
    asm volatile("ld.shared.b32 %0, [%1];" : "=r"(r) : "r"(addr))

// =====================================================================
// elementwise tf32 round
// =====================================================================
__global__ __launch_bounds__(256) void cvt_tf32(const float* __restrict__ in,
                                                float* __restrict__ out, int n)
{
    const int i = (blockIdx.x * 256 + threadIdx.x) * 4;
    if (i >= n) return;
    float4 v = *(const float4*)(in + i);
    v.x = tf32rf(v.x); v.y = tf32rf(v.y); v.z = tf32rf(v.z); v.w = tf32rf(v.w);
    *(float4*)(out + i) = v;
}

// =====================================================================
// tf32 mma.sync GEMM: C[M,N] = A[M,K] * B[N,K]^T + bias[N]   (from R11)
// =====================================================================
#define GSTAGE 32768
#define GSM    (3*GSTAGE)

__device__ __forceinline__ void g_load_stage(
    const float* __restrict__ A, const float* __restrict__ B,
    int N, int K, int bm, int bn, int k0,
    uint32_t sA, uint32_t sB, int tid)
{
#pragma unroll
    for (int i = 0; i < 4; ++i) {
        const int c = tid + i * 256;
        const int row = c >> 3, j = c & 7;
        const uint32_t soff = (uint32_t)(row * 128 + ((j ^ (row & 7)) << 4));
        cpa16(sA + soff, A + (size_t)(bm + row) * K + k0 + j * 4);
        const int gr = bn + row;
        const bool ok = gr < N;
        cpa16z(sB + soff, B + (size_t)(ok ? gr : 0) * K + k0 + j * 4, ok ? 16 : 0);
    }
}

__global__ __launch_bounds__(256, 2) void gemm_mma(
    const float* __restrict__ A, const float* __restrict__ B,
    const float* __restrict__ bias, float* __restrict__ C,
    int M, int N, int K)
{
    extern __shared__ __align__(128) char smg[];
    const uint32_t sb = (uint32_t)__cvta_generic_to_shared(smg);
    const int tid = threadIdx.x, lane = tid & 31, w = tid >> 5;
    const int wm = w & 1, wn = w >> 1;
    const int bm = blockIdx.y * 128, bn = blockIdx.x * 128;

    float acc[4][4][4];
#pragma unroll
    for (int mi = 0; mi < 4; ++mi)
#pragma unroll
        for (int nj = 0; nj < 4; ++nj)
#pragma unroll
            for (int r = 0; r < 4; ++r) acc[mi][nj][r] = 0.f;

    const int nk = K >> 5;

#pragma unroll
    for (int s = 0; s < 2; ++s) {
        g_load_stage(A, B, N, K, bm, bn, s * 32, sb + s * GSTAGE, sb + s * GSTAGE + 16384, tid);
        asm volatile("cp.async.commit_group;" ::: "memory");
    }

    for (int t = 0; t < nk; ++t) {
        asm volatile("cp.async.wait_group 1;" ::: "memory");
        __syncthreads();

        const int tn = t + 2;
        if (tn < nk) {
            const uint32_t so = sb + (uint32_t)(tn % 3) * GSTAGE;
            g_load_stage(A, B, N, K, bm, bn, tn * 32, so, so + 16384, tid);
        }
        asm volatile("cp.async.commit_group;" ::: "memory");

        const uint32_t sA = sb + (uint32_t)(t % 3) * GSTAGE;
        const uint32_t sB = sA + 16384;

#pragma unroll
        for (int ks = 0; ks < 4; ++ks) {
            uint32_t af[4][4];
#pragma unroll
            for (int mi = 0; mi < 4; ++mi) {
                const int mat = lane >> 3;
                const int row = wm * 64 + mi * 16 + (lane & 7) + ((mat & 1) << 3);
                const int chunk = 2 * ks + (mat >> 1);
                const uint32_t ad = sA + (uint32_t)(row * 128 + ((chunk ^ (row & 7)) << 4));
                LDMX4(af[mi], ad);
            }
            uint32_t bf[4][2];
#pragma unroll
            for (int nj = 0; nj < 4; ++nj) {
                const int n  = wn * 32 + nj * 8 + (lane >> 2);
                const uint32_t b0a = sB + (uint32_t)(n * 128 + (((2*ks)   ^ (n & 7)) << 4) + ((lane & 3) << 2));
                const uint32_t b1a = sB + (uint32_t)(n * 128 + (((2*ks+1) ^ (n & 7)) << 4) + ((lane & 3) << 2));
                LDS32(bf[nj][0], b0a);
                LDS32(bf[nj][1], b1a);
            }
#pragma unroll
            for (int mi = 0; mi < 4; ++mi)
#pragma unroll
                for (int nj = 0; nj < 4; ++nj)
                    mma_tf32(acc[mi][nj], af[mi], bf[nj]);
        }
    }

#pragma unroll
    for (int mi = 0; mi < 4; ++mi) {
        const int r0 = bm + wm * 64 + mi * 16 + (lane >> 2);
#pragma unroll
        for (int nj = 0; nj < 4; ++nj) {
            const int c0 = bn + wn * 32 + nj * 8 + ((lane & 3) << 1);
            if (c0 < N) {
                const float b0 = bias[c0], b1 = bias[c0 + 1];
                float2 v0 = make_float2(acc[mi][nj][0] + b0, acc[mi][nj][1] + b1);
                float2 v1 = make_float2(acc[mi][nj][2] + b0, acc[mi][nj][3] + b1);
                *(float2*)(C + (size_t)r0 * N + c0)       = v0;
                *(float2*)(C + (size_t)(r0 + 8) * N + c0) = v1;
            }
        }
    }
}

// =====================================================================
// RMSNorm (emits tf32-rounded output)
// =====================================================================
__global__ __launch_bounds__(256) void rmsnorm_kernel(
    const float* __restrict__ in, int ldin,
    const float* __restrict__ w,
    float* __restrict__ out, int ldout, int N)
{
    const float* x = in  + (size_t)blockIdx.x * ldin;
    float*       y = out + (size_t)blockIdx.x * ldout;
    float ss = 0.f;
    for (int i = threadIdx.x; i < N; i += 256) { float v = x[i]; ss = fmaf(v, v, ss); }
#pragma unroll
    for (int off = 16; off; off >>= 1) ss += __shfl_xor_sync(0xffffffffu, ss, off);
    __shared__ float red[8];
    __shared__ float s_inv;
    if ((threadIdx.x & 31) == 0) red[threadIdx.x >> 5] = ss;
    __syncthreads();
    if (threadIdx.x == 0) {
        float tot = 0.f;
#pragma unroll
        for (int k = 0; k < 8; k++) tot += red[k];
        s_inv = rsqrtf(tot / (float)N + 1e-6f);
    }
    __syncthreads();
    const float inv = s_inv;
    for (int i = threadIdx.x; i < N; i += 256) y[i] = tf32rf(x[i] * inv * w[i]);
}

// =====================================================================
// RoPE
// =====================================================================
#define L2_10K_DIV32 0.4152410118609203f

__global__ __launch_bounds__(256) void rope_q_kernel(float* __restrict__ q)
{
    const int idx = blockIdx.x * 256 + threadIdx.x;
    if (idx >= T_ * NH_ * 32) return;
    const int i = idx & 31;
    const int h = (idx >> 5) & 15;
    const int t = idx >> 9;
    const int pos = t & (SEQ_ - 1);
    const float invf = exp2f(-(float)i * L2_10K_DIV32);
    float s, c;
    sincosf((float)pos * invf, &s, &c);
    float* p = q + (size_t)t * (NH_*QKHD_) + h * QKHD_ + NOPE_;
    const float x1 = p[i], x2 = p[32 + i];
    p[i]      = x1 * c - x2 * s;
    p[32 + i] = x2 * c + x1 * s;
}

__global__ __launch_bounds__(256) void rope_k_kernel(float* __restrict__ kva)
{
    const int idx = blockIdx.x * 256 + threadIdx.x;
    if (idx >= T_ * 32) return;
    const int i = idx & 31;
    const int t = idx >> 5;
    const int pos = t & (SEQ_ - 1);
    const float invf = exp2f(-(float)i * L2_10K_DIV32);
    float s, c;
    sincosf((float)pos * invf, &s, &c);
    float* p = kva + (size_t)t * (KVLORA_+ROPE_) + KVLORA_;
    const float x1 = p[i], x2 = p[32 + i];
    p[i]      = x1 * c - x2 * s;
    p[32 + i] = x2 * c + x1 * s;
}

// =====================================================================
// Tensor-core causal flash attention (tf32 mma.sync).
// Grid (16 qtiles, 16 heads, 2 batch), 256 threads (8 warps).
// Warp w owns q-rows 16w..16w+15 of the 128-row tile.
// smem: 4 x 16KB chunk buffers (QK double-buffer; later P staging)
//       + V^T tile 128x132 floats.
// =====================================================================
#define ATT_VT  65536u
#define ATT_SM  (65536 + 128*132*4)   // 133120 bytes

__device__ __forceinline__ void att_load_chunk(
    const float* __restrict__ Qb, const float* __restrict__ KVb,
    const float* __restrict__ KVa,
    int q_t0, int k_t0, int h, int dc,
    uint32_t sQ, uint32_t sK, int tid)
{
#pragma unroll
    for (int i = 0; i < 4; ++i) {
        const int c = tid + i * 256;        // 0..1023
        const int row = c >> 3, j = c & 7;
        const uint32_t soff = (uint32_t)(row * 128 + ((j ^ (row & 7)) << 4));
        cpa16(sQ + soff, Qb + (size_t)(q_t0 + row) * (NH_*QKHD_) + h * QKHD_ + dc + j * 4);
        const int d = dc + j * 4;
        const float* kp = (d < NOPE_)
            ? (KVb + (size_t)(k_t0 + row) * 4096 + h * 256 + d)
            : (KVa + (size_t)(k_t0 + row) * (KVLORA_+ROPE_) + KVLORA_ + (d - NOPE_));
        cpa16(sK + soff, kp);
    }
}

__global__ __launch_bounds__(256, 1) void mla_attn_mma(
    const float* __restrict__ Qb, const float* __restrict__ KVb,
    const float* __restrict__ KVa, float* __restrict__ Ob)
{
    extern __shared__ __align__(128) char sma[];
    const uint32_t sb = (uint32_t)__cvta_generic_to_shared(sma);
    float* VtF = (float*)(sma + ATT_VT);

    const int qt = (int)gridDim.x - 1 - (int)blockIdx.x;   // longest first
    const int h = blockIdx.y, b = blockIdx.z;
    const int tid = threadIdx.x, lane = tid & 31, w = tid >> 5;
    const int q_t0 = b * SEQ_ + qt * 128;
    const float scale = 0.07216878364870323f;   // 1/sqrt(192)

    float accO[16][4];
#pragma unroll
    for (int t = 0; t < 16; ++t)
#pragma unroll
        for (int r = 0; r < 4; ++r) accO[t][r] = 0.f;
    float mA = -1e30f, mB = -1e30f, lA = 0.f, lB = 0.f;

    for (int kt = 0; kt <= qt; ++kt) {
        const int k_t0 = b * SEQ_ + kt * 128;

        // prologue: chunks 0,1 into stages 0,1
#pragma unroll
        for (int s = 0; s < 2; ++s) {
            att_load_chunk(Qb, KVb, KVa, q_t0, k_t0, h, s * 32,
                           sb + (uint32_t)s * 32768u, sb + (uint32_t)s * 32768u + 16384u, tid);
            asm volatile("cp.async.commit_group;" ::: "memory");
        }

        // V^T fill (transposed, tf32-rna rounded) — overlaps cp.async
        {
            const int k = tid & 127, half = tid >> 7;
            const float* vp = KVb + (size_t)(k_t0 + k) * 4096 + h * 256 + 128 + half * 64;
#pragma unroll
            for (int i = 0; i < 16; ++i) {
                float4 v = *(const float4*)(vp + i * 4);
                const int vd = half * 64 + i * 4;
                VtF[(vd+0)*132 + k] = tf32rf(v.x);
                VtF[(vd+1)*132 + k] = tf32rf(v.y);
                VtF[(vd+2)*132 + k] = tf32rf(v.z);
                VtF[(vd+3)*132 + k] = tf32rf(v.w);
            }
        }

        // ---- S = Q K^T over d=192 (6 chunks, double-buffered) ----
        float accS[16][4];
#pragma unroll
        for (int t = 0; t < 16; ++t)
#pragma unroll
            for (int r = 0; r < 4; ++r) accS[t][r] = 0.f;

        for (int c = 0; c < 6; ++c) {
            asm volatile("cp.async.wait_group 1;" ::: "memory");
            __syncthreads();

            const uint32_t sQ = sb + (uint32_t)(c & 1) * 32768u;
            const uint32_t sK = sQ + 16384u;
#pragma unroll
            for (int ks = 0; ks < 4; ++ks) {
                uint32_t af[4];
                const int mat = lane >> 3;
                const int row = 16 * w + (lane & 7) + ((mat & 1) << 3);
                const int chunk = 2 * ks + (mat >> 1);
                LDMX4(af, sQ + (uint32_t)(row * 128 + ((chunk ^ (row & 7)) << 4)));
#pragma unroll
                for (int t = 0; t < 16; ++t) {
                    const int n = t * 8 + (lane >> 2);
                    uint32_t bf[2];
                    LDS32(bf[0], sK + (uint32_t)(n * 128 + (((2*ks)   ^ (n & 7)) << 4) + ((lane & 3) << 2)));
                    LDS32(bf[1], sK + (uint32_t)(n * 128 + (((2*ks+1) ^ (n & 7)) << 4) + ((lane & 3) << 2)));
                    mma_tf32(accS[t], af, bf);
                }
            }
            __syncthreads();
            if (c + 2 < 6) {
                const uint32_t so = sb + (uint32_t)(c & 1) * 32768u;
                att_load_chunk(Qb, KVb, KVa, q_t0, k_t0, h, (c + 2) * 32, so, so + 16384u, tid);
            }
            asm volatile("cp.async.commit_group;" ::: "memory");
        }
        __syncthreads();   // all warps done with chunk bufs; Vt complete

        // ---- scale + causal mask + online softmax (rows in 4-lane groups) ----
        float mxA = -1e30f, mxB = -1e30f;
        const int rlA = 16 * w + (lane >> 2), rlB = rlA + 8;
#pragma unroll
        for (int t = 0; t < 16; ++t) {
            float s0 = accS[t][0] * scale, s1 = accS[t][1] * scale;
            float s2 = accS[t][2] * scale, s3 = accS[t][3] * scale;
            if (kt == qt) {
                const int c0 = t * 8 + ((lane & 3) << 1);
                if (c0     > rlA) s0 = -1e30f;
                if (c0 + 1 > rlA) s1 = -1e30f;
                if (c0     > rlB) s2 = -1e30f;
                if (c0 + 1 > rlB) s3 = -1e30f;
            }
            accS[t][0] = s0; accS[t][1] = s1; accS[t][2] = s2; accS[t][3] = s3;
            mxA = fmaxf(mxA, fmaxf(s0, s1));
            mxB = fmaxf(mxB, fmaxf(s2, s3));
        }
        mxA = fmaxf(mxA, __shfl_xor_sync(0xffffffffu, mxA, 1));
        mxA = fmaxf(mxA, __shfl_xor_sync(0xffffffffu, mxA, 2));
        mxB = fmaxf(mxB, __shfl_xor_sync(0xffffffffu, mxB, 1));
        mxB = fmaxf(mxB, __shfl_xor_sync(0xffffffffu, mxB, 2));

        const float mnA = fmaxf(mA, mxA), mnB = fmaxf(mB, mxB);
        const float cA = __expf(mA - mnA), cB = __expf(mB - mnB);
        float sumA = 0.f, sumB = 0.f;
#pragma unroll
        for (int t = 0; t < 16; ++t) {
            accO[t][0] *= cA; accO[t][1] *= cA;
            accO[t][2] *= cB; accO[t][3] *= cB;
            const float p0 = __expf(accS[t][0] - mnA);
            const float p1 = __expf(accS[t][1] - mnA);
            const float p2 = __expf(accS[t][2] - mnB);
            const float p3 = __expf(accS[t][3] - mnB);
            accS[t][0] = p0; accS[t][1] = p1; accS[t][2] = p2; accS[t][3] = p3;
            sumA += p0 + p1; sumB += p2 + p3;
        }
        sumA += __shfl_xor_sync(0xffffffffu, sumA, 1);
        sumA += __shfl_xor_sync(0xffffffffu, sumA, 2);
        sumB += __shfl_xor_sync(0xffffffffu, sumB, 1);
        sumB += __shfl_xor_sync(0xffffffffu, sumB, 2);
        lA = lA * cA + sumA; lB = lB * cB + sumB;
        mA = mnA; mB = mnB;

        // ---- write P (tf32-rounded) into chunk buffers, GEMM-A swizzled ----
        {
            const int e2 = (lane & 3) << 1;
#pragma unroll
            for (int t = 0; t < 16; ++t) {
                const int k0 = t * 8 + e2;
#pragma unroll
                for (int r = 0; r < 4; ++r) {
                    const int rr = (r < 2) ? rlA : rlB;
                    const int k  = k0 + (r & 1);
                    const int kk = k & 31;
                    char* p = sma + (k >> 5) * 16384 + rr * 128
                            + (((kk >> 2) ^ (rr & 7)) << 4) + ((kk & 3) << 2);
                    *(float*)p = tf32rf(accS[t][r]);
                }
            }
        }
        __syncwarp();

        // ---- O += P * V^T ----
#pragma unroll
        for (int pb = 0; pb < 4; ++pb) {
            const uint32_t sP = sb + (uint32_t)pb * 16384u;
#pragma unroll
            for (int ks = 0; ks < 4; ++ks) {
                uint32_t af[4];
                const int mat = lane >> 3;
                const int row = 16 * w + (lane & 7) + ((mat & 1) << 3);
                const int chunk = 2 * ks + (mat >> 1);
                LDMX4(af, sP + (uint32_t)(row * 128 + ((chunk ^ (row & 7)) << 4)));
                const int kbase = pb * 32 + ks * 8 + (lane & 3);
#pragma unroll
                for (int t = 0; t < 16; ++t) {
                    const int n = t * 8 + (lane >> 2);
                    uint32_t bf[2];
                    bf[0] = __float_as_uint(VtF[n * 132 + kbase]);
                    bf[1] = __float_as_uint(VtF[n * 132 + kbase + 4]);
                    mma_tf32(accO[t], af, bf);
                }
            }
        }
        __syncthreads();   // before next kt overwrites bufs/Vt
    }

    // ---- epilogue: O/l -> g_att (tf32-rounded for o-proj) ----
    const float ivA = 1.f / lA, ivB = 1.f / lB;
    const size_t rowA = (size_t)(q_t0 + 16 * w + (lane >> 2));
    const size_t rowB = rowA + 8;
#pragma unroll
    for (int t = 0; t < 16; ++t) {
        const int col = h * 128 + t * 8 + ((lane & 3) << 1);
        float2 v0 = make_float2(tf32rf(accO[t][0] * ivA), tf32rf(accO[t][1] * ivA));
        float2 v1 = make_float2(tf32rf(accO[t][2] * ivB), tf32rf(accO[t][3] * ivB));
        *(float2*)(Ob + rowA * (NH_*VHD_) + col) = v0;
        *(float2*)(Ob + rowB * (NH_*VHD_) + col) = v1;
    }
}

// =====================================================================
// launch
// =====================================================================
extern "C" void kernel_launch(void* const* d_in, const int* in_sizes, int n_in,
                              void* d_out, int out_size)
{
    const float* x      = (const float*)d_in[0];
    const float* wqa    = (const float*)d_in[1];
    const float* wqa_b  = (const float*)d_in[2];
    const float* qnw    = (const float*)d_in[3];
    const float* wqb    = (const float*)d_in[4];
    const float* wqb_b  = (const float*)d_in[5];
    const float* wkva   = (const float*)d_in[6];
    const float* wkva_b = (const float*)d_in[7];
    const float* kvnw   = (const float*)d_in[8];
    const float* wkvb   = (const float*)d_in[9];
    const float* wkvb_b = (const float*)d_in[10];
    const float* wo     = (const float*)d_in[11];
    const float* wo_b   = (const float*)d_in[12];
    float* out = (float*)d_out;

    float *p_qa, *p_q, *p_kva, *p_kvn, *p_kvb, *p_att;
    float *p_xt, *p_wqat, *p_wqbt, *p_wkvat, *p_wkvbt, *p_wot;
    cudaGetSymbolAddress((void**)&p_qa,   g_qa);
    cudaGetSymbolAddress((void**)&p_q,    g_q);
    cudaGetSymbolAddress((void**)&p_kva,  g_kva);
    cudaGetSymbolAddress((void**)&p_kvn,  g_kvn);
    cudaGetSymbolAddress((void**)&p_kvb,  g_kvb);
    cudaGetSymbolAddress((void**)&p_att,  g_att);
    cudaGetSymbolAddress((void**)&p_xt,   g_xt);
    cudaGetSymbolAddress((void**)&p_wqat, g_wqat);
    cudaGetSymbolAddress((void**)&p_wqbt, g_wqbt);
    cudaGetSymbolAddress((void**)&p_wkvat,g_wkvat);
    cudaGetSymbolAddress((void**)&p_wkvbt,g_wkvbt);
    cudaGetSymbolAddress((void**)&p_wot,  g_wot);

    cudaFuncSetAttribute(gemm_mma,     cudaFuncAttributeMaxDynamicSharedMemorySize, GSM);
    cudaFuncSetAttribute(mla_attn_mma, cudaFuncAttributeMaxDynamicSharedMemorySize, ATT_SM);

    const dim3 blk256(256);
    const int mt = T_ / 128;  // 32

    // pre-round operands to tf32 (rna)
    cvt_tf32<<<(T_*DIM_)/1024, blk256>>>(x,    p_xt,    T_*DIM_);
    cvt_tf32<<<(QLORA_*DIM_)/1024, blk256>>>(wqa,  p_wqat,  QLORA_*DIM_);
    cvt_tf32<<<(NH_*QKHD_*QLORA_)/1024, blk256>>>(wqb,  p_wqbt,  NH_*QKHD_*QLORA_);
    cvt_tf32<<<((KVLORA_+ROPE_)*DIM_)/1024, blk256>>>(wkva, p_wkvat, (KVLORA_+ROPE_)*DIM_);
    cvt_tf32<<<(NH_*(NOPE_+VHD_)*KVLORA_)/1024, blk256>>>(wkvb, p_wkvbt, NH_*(NOPE_+VHD_)*KVLORA_);
    cvt_tf32<<<(DIM_*NH_*VHD_)/1024, blk256>>>(wo,   p_wot,   DIM_*NH_*VHD_);

    // Q path
    gemm_mma<<<dim3(QLORA_/128, mt), blk256, GSM>>>(p_xt, p_wqat, wqa_b, p_qa, T_, QLORA_, DIM_);
    rmsnorm_kernel<<<T_, blk256>>>(p_qa, QLORA_, qnw, p_qa, QLORA_, QLORA_);
    gemm_mma<<<dim3((NH_*QKHD_)/128, mt), blk256, GSM>>>(p_qa, p_wqbt, wqb_b, p_q, T_, NH_*QKHD_, QLORA_);
    rope_q_kernel<<<(T_*NH_*32)/256, blk256>>>(p_q);

    // KV path
    gemm_mma<<<dim3((KVLORA_+ROPE_+127)/128, mt), blk256, GSM>>>(p_xt, p_wkvat, wkva_b, p_kva, T_, KVLORA_+ROPE_, DIM_);
    rope_k_kernel<<<(T_*32)/256, blk256>>>(p_kva);
    rmsnorm_kernel<<<T_, blk256>>>(p_kva, KVLORA_+ROPE_, kvnw, p_kvn, KVLORA_, KVLORA_);
    gemm_mma<<<dim3((NH_*(NOPE_+VHD_))/128, mt), blk256, GSM>>>(p_kvn, p_wkvbt, wkvb_b, p_kvb, T_, NH_*(NOPE_+VHD_), KVLORA_);

    // Attention (tensor-core tf32)
    mla_attn_mma<<<dim3(SEQ_/128, NH_, BS_), blk256, ATT_SM>>>(p_q, p_kvb, p_kva, p_att);

    // Output projection
    gemm_mma<<<dim3(DIM_/128, mt), blk256, GSM>>>(p_att, p_wot, wo_b, out, T_, DIM_, NH_*VHD_);
}